// round 16
// baseline (speedup 1.0000x reference)
#include <cuda_runtime.h>
#include <cuda_bf16.h>
#include <cstdint>

#define M_CONST    100
#define GROUPS     25     // M/4 float4 groups per row
#define ROWS_ITER  10     // row slots (250 active threads)
#define ACTIVE     (GROUPS * ROWS_ITER)
#define CHUNK_ROWS 148    // grid = ceil(131072/148) = 886 <= 148 SMs x 6 CTAs
#define PAIR_STRIDE (2 * ROWS_ITER)

__device__ __forceinline__ float ex2_(float x) {
    float r; asm("ex2.approx.f32 %0, %1;" : "=f"(r) : "f"(x)); return r;
}
__device__ __forceinline__ float rcp_(float x) {
    float r; asm("rcp.approx.f32 %0, %1;" : "=f"(r) : "f"(x)); return r;
}

#define SQRT_HL2E    0.8493218002880191f   // sqrt(0.5*log2(e)) folded into dx,dy
#define LOG2_INV_2PI -2.651496129472319f   // log2(1/(2*pi)) folded into ex2 arg

// basis_sigma is diagonal (reference: vmap(diag)(var)).
// Per-row setup hoisted to a block prologue; hot loop = two independent rows
// per iteration, pointer-increment addressing, 1/(2pi) folded into EX2 arg:
//   r = ex2( -num'*rs^2 + log2(1/2pi) ) * rs
// 6 CTAs/SM (launch_bounds cap) and a grid of exactly one resident wave.
__global__ __launch_bounds__(256, 6) void ContinuousSoftmax_kernel(
    const float* __restrict__ theta,        // [N,6]
    const float* __restrict__ basis_mu,     // [M,2]
    const float* __restrict__ basis_sigma,  // [M,2,2] diagonal
    float* __restrict__ out,                // [N,M]
    int N)
{
    __shared__ float4 spA[CHUNK_ROWS];   // s00, s11, mu0', mu1'
    __shared__ float2 spB[CHUNK_ROWS];   // ns01q, s01_2

    const int tid   = threadIdx.x;
    const int row0  = blockIdx.x * CHUNK_ROWS;
    const int nrows = (N - row0 < CHUNK_ROWS) ? (N - row0) : CHUNK_ROWS;

    // ---- prologue: parallel row setups (one MUFU.RCP each) ----
    for (int rr = tid; rr < nrows; rr += 256) {
        const float2* th = reinterpret_cast<const float2*>(theta)
                           + (size_t)(row0 + rr) * 3;
        const float2 e  = th[0];
        const float2 q0 = th[1];
        const float2 q1 = th[2];
        const float d   = q0.x * q1.y - q0.y * q1.x;
        const float r   = rcp_(d);                    // MUFU.RCP
        const float u01 = -0.5f * (q0.y + q1.x);
        const float m0p = q1.y * e.x + u01 * e.y;     // overlap RCP latency
        const float m1p = u01 * e.x + q0.x * e.y;
        const float inv = -0.5f * r;                  // = -1/(2d)
        const float s00 = q1.y * inv;
        const float s11 = q0.x * inv;
        const float s01 = u01  * inv;
        const float mu0 = m0p * inv;
        const float mu1 = m1p * inv;
        spA[rr] = make_float4(s00, s11, mu0 * SQRT_HL2E, mu1 * SQRT_HL2E);
        spB[rr] = make_float2(-(s01 * s01), s01 + s01);
    }
    __syncthreads();

    if (tid >= ACTIVE) return;
    const int r_local = tid / GROUPS;             // 0..9
    const int g       = tid - r_local * GROUPS;   // 0..24

    // ---- one-time: cache this thread's 4 basis entries in registers ----
    const float4* bm = reinterpret_cast<const float4*>(basis_mu) + 2 * g;
    const float4  m01 = bm[0];
    const float4  m23 = bm[1];
    const float4* bs = reinterpret_cast<const float4*>(basis_sigma) + 4 * g;
    const float4  sg0 = bs[0], sg1 = bs[1], sg2 = bs[2], sg3 = bs[3];

    // basis means pre-scaled by sqrt(K) and negated (dx' = mu0' + nbm0')
    const float nbm0[4] = {-m01.x * SQRT_HL2E, -m01.z * SQRT_HL2E,
                           -m23.x * SQRT_HL2E, -m23.z * SQRT_HL2E};
    const float nbm1[4] = {-m01.y * SQRT_HL2E, -m01.w * SQRT_HL2E,
                           -m23.y * SQRT_HL2E, -m23.w * SQRT_HL2E};
    const float av[4]   = {sg0.x, sg1.x, sg2.x, sg3.x};   // diag var_x
    const float bv[4]   = {sg0.w, sg1.w, sg2.w, sg3.w};   // diag var_y

    // pointer-increment addressing: bases computed once, IADD per iteration
    float* po = out + (size_t)(row0 + r_local) * M_CONST + 4 * g;
    const float4* pa = spA + r_local;
    const float2* pb = spB + r_local;

    for (int rr = r_local; rr < nrows; rr += PAIR_STRIDE) {
        const bool hasB = (rr + ROWS_ITER) < nrows;
        const int  offB = hasB ? ROWS_ITER : 0;   // clamp (dup compute, guarded store)

        const float4 A0 = pa[0];                  // LDS broadcast
        const float2 C0 = pb[0];
        const float4 A1 = pa[offB];
        const float2 C1 = pb[offB];

        float resA[4], resB[4];
        #pragma unroll
        for (int k = 0; k < 4; ++k) {
            // row A chain
            const float a_c00 = A0.x + av[k];
            const float a_c11 = A0.y + bv[k];
            const float a_dx  = A0.z + nbm0[k];
            const float a_dy  = A0.w + nbm1[k];
            const float a_det = fmaf(a_c00, a_c11, C0.x);
            const float a_rs  = rsqrtf(a_det);    // MUFU.RSQ
            // row B chain (independent: fills A's RSQ shadow)
            const float b_c00 = A1.x + av[k];
            const float b_c11 = A1.y + bv[k];
            const float b_dx  = A1.z + nbm0[k];
            const float b_dy  = A1.w + nbm1[k];
            const float b_det = fmaf(b_c00, b_c11, C1.x);
            const float b_rs  = rsqrtf(b_det);

            // numerators overlap the RSQ latencies
            const float a_in  = fmaf(a_c11, a_dx, -(C0.y * a_dy));
            const float a_num = fmaf(a_c00 * a_dy, a_dy, a_dx * a_in);
            const float b_in  = fmaf(b_c11, b_dx, -(C1.y * b_dy));
            const float b_num = fmaf(b_c00 * b_dy, b_dy, b_dx * b_in);

            const float a_r2  = a_rs * a_rs;
            const float b_r2  = b_rs * b_rs;
            const float a_arg = fmaf(a_num, -a_r2, LOG2_INV_2PI);
            const float b_arg = fmaf(b_num, -b_r2, LOG2_INV_2PI);
            resA[k] = ex2_(a_arg) * a_rs;         // MUFU.EX2
            resB[k] = ex2_(b_arg) * b_rs;
        }
        *reinterpret_cast<float4*>(po) =
            make_float4(resA[0], resA[1], resA[2], resA[3]);
        if (hasB)
            *reinterpret_cast<float4*>(po + ROWS_ITER * M_CONST) =
                make_float4(resB[0], resB[1], resB[2], resB[3]);

        po += PAIR_STRIDE * M_CONST;
        pa += PAIR_STRIDE;
        pb += PAIR_STRIDE;
    }
}

extern "C" void kernel_launch(void* const* d_in, const int* in_sizes, int n_in,
                              void* d_out, int out_size) {
    const float* theta       = (const float*)d_in[0];
    const float* basis_mu    = (const float*)d_in[1];
    const float* basis_sigma = (const float*)d_in[2];
    float* out = (float*)d_out;

    const int N = in_sizes[0] / 6;

    const int threads = 256;
    const int blocks  = (N + CHUNK_ROWS - 1) / CHUNK_ROWS;   // 886 for N=131072
    ContinuousSoftmax_kernel<<<blocks, threads>>>(theta, basis_mu, basis_sigma,
                                                  out, N);
}

// round 17
// speedup vs baseline: 1.1193x; 1.1193x over previous
#include <cuda_runtime.h>
#include <cuda_bf16.h>
#include <cstdint>

#define M_CONST    100
#define GROUPS     25     // M/4 float4 groups per row
#define ROWS_ITER  10     // row slots (250 active threads)
#define ACTIVE     (GROUPS * ROWS_ITER)
#define CHUNK_ROWS 180    // grid 729 ~= one wave at 5 CTAs/SM
#define PAIR_STRIDE (2 * ROWS_ITER)
#define FULL_ITERS (CHUNK_ROWS / PAIR_STRIDE)   // 9, uniform for all r_local

__device__ __forceinline__ float ex2_(float x) {
    float r; asm("ex2.approx.f32 %0, %1;" : "=f"(r) : "f"(x)); return r;
}
__device__ __forceinline__ float rcp_(float x) {
    float r; asm("rcp.approx.f32 %0, %1;" : "=f"(r) : "f"(x)); return r;
}

#define SQRT_HL2E    0.8493218002880191f   // sqrt(0.5*log2(e)) folded into dx,dy
#define LOG2_INV_2PI -2.651496129472319f   // log2(1/(2*pi)) folded into ex2 arg

// Two-row element-pair body: reads row params A0/C0 (row rr) and A1/C1
// (row rr+10), computes 4+4 results, stores one/two float4s.
struct BasisRegs {
    float nbm0[4], nbm1[4], av[4], bv[4];
};

__device__ __forceinline__ void pair_body(
    const float4 A0, const float2 C0, const float4 A1, const float2 C1,
    const BasisRegs& B, float* po, bool storeB)
{
    float resA[4], resB[4];
    #pragma unroll
    for (int k = 0; k < 4; ++k) {
        const float a_c00 = A0.x + B.av[k];
        const float a_c11 = A0.y + B.bv[k];
        const float a_dx  = A0.z + B.nbm0[k];
        const float a_dy  = A0.w + B.nbm1[k];
        const float a_det = fmaf(a_c00, a_c11, C0.x);
        const float a_rs  = rsqrtf(a_det);        // MUFU.RSQ
        const float b_c00 = A1.x + B.av[k];
        const float b_c11 = A1.y + B.bv[k];
        const float b_dx  = A1.z + B.nbm0[k];
        const float b_dy  = A1.w + B.nbm1[k];
        const float b_det = fmaf(b_c00, b_c11, C1.x);
        const float b_rs  = rsqrtf(b_det);

        const float a_in  = fmaf(a_c11, a_dx, -(C0.y * a_dy));
        const float a_num = fmaf(a_c00 * a_dy, a_dy, a_dx * a_in);
        const float b_in  = fmaf(b_c11, b_dx, -(C1.y * b_dy));
        const float b_num = fmaf(b_c00 * b_dy, b_dy, b_dx * b_in);

        const float a_arg = fmaf(a_num, -(a_rs * a_rs), LOG2_INV_2PI);
        const float b_arg = fmaf(b_num, -(b_rs * b_rs), LOG2_INV_2PI);
        resA[k] = ex2_(a_arg) * a_rs;             // MUFU.EX2
        resB[k] = ex2_(b_arg) * b_rs;
    }
    *reinterpret_cast<float4*>(po) =
        make_float4(resA[0], resA[1], resA[2], resA[3]);
    if (storeB)
        *reinterpret_cast<float4*>(po + ROWS_ITER * M_CONST) =
            make_float4(resB[0], resB[1], resB[2], resB[3]);
}

// basis_sigma is diagonal (reference: vmap(diag)(var)).
// Per-row setup hoisted to a block prologue. Hot path: full blocks have a
// UNIFORM trip count (9 pair-iterations) -> fully unrolled specialized loop.
__global__ __launch_bounds__(256, 5) void ContinuousSoftmax_kernel(
    const float* __restrict__ theta,        // [N,6]
    const float* __restrict__ basis_mu,     // [M,2]
    const float* __restrict__ basis_sigma,  // [M,2,2] diagonal
    float* __restrict__ out,                // [N,M]
    int N)
{
    __shared__ float4 spA[CHUNK_ROWS];   // s00, s11, mu0', mu1'
    __shared__ float2 spB[CHUNK_ROWS];   // ns01q, s01_2

    const int tid   = threadIdx.x;
    const int row0  = blockIdx.x * CHUNK_ROWS;
    const int nrows = (N - row0 < CHUNK_ROWS) ? (N - row0) : CHUNK_ROWS;

    // ---- prologue: parallel row setups (one MUFU.RCP each) ----
    for (int rr = tid; rr < nrows; rr += 256) {
        const float2* th = reinterpret_cast<const float2*>(theta)
                           + (size_t)(row0 + rr) * 3;
        const float2 e  = th[0];
        const float2 q0 = th[1];
        const float2 q1 = th[2];
        const float d   = q0.x * q1.y - q0.y * q1.x;
        const float r   = rcp_(d);                    // MUFU.RCP
        const float u01 = -0.5f * (q0.y + q1.x);
        const float m0p = q1.y * e.x + u01 * e.y;     // overlap RCP latency
        const float m1p = u01 * e.x + q0.x * e.y;
        const float inv = -0.5f * r;                  // = -1/(2d)
        const float s00 = q1.y * inv;
        const float s11 = q0.x * inv;
        const float s01 = u01  * inv;
        const float mu0 = m0p * inv;
        const float mu1 = m1p * inv;
        spA[rr] = make_float4(s00, s11, mu0 * SQRT_HL2E, mu1 * SQRT_HL2E);
        spB[rr] = make_float2(-(s01 * s01), s01 + s01);
    }
    __syncthreads();

    if (tid >= ACTIVE) return;
    const int r_local = tid / GROUPS;             // 0..9
    const int g       = tid - r_local * GROUPS;   // 0..24

    // ---- one-time: cache this thread's 4 basis entries in registers ----
    const float4* bm = reinterpret_cast<const float4*>(basis_mu) + 2 * g;
    const float4  m01 = bm[0];
    const float4  m23 = bm[1];
    const float4* bs = reinterpret_cast<const float4*>(basis_sigma) + 4 * g;
    const float4  sg0 = bs[0], sg1 = bs[1], sg2 = bs[2], sg3 = bs[3];

    BasisRegs B;
    B.nbm0[0] = -m01.x * SQRT_HL2E; B.nbm0[1] = -m01.z * SQRT_HL2E;
    B.nbm0[2] = -m23.x * SQRT_HL2E; B.nbm0[3] = -m23.z * SQRT_HL2E;
    B.nbm1[0] = -m01.y * SQRT_HL2E; B.nbm1[1] = -m01.w * SQRT_HL2E;
    B.nbm1[2] = -m23.y * SQRT_HL2E; B.nbm1[3] = -m23.w * SQRT_HL2E;
    B.av[0] = sg0.x; B.av[1] = sg1.x; B.av[2] = sg2.x; B.av[3] = sg3.x;
    B.bv[0] = sg0.w; B.bv[1] = sg1.w; B.bv[2] = sg2.w; B.bv[3] = sg3.w;

    float* po = out + (size_t)(row0 + r_local) * M_CONST + 4 * g;
    const float4* pa = spA + r_local;
    const float2* pb = spB + r_local;

    if (nrows == CHUNK_ROWS) {
        // full chunk: uniform trip count -> fully unrolled, B-row always valid
        #pragma unroll
        for (int it = 0; it < FULL_ITERS; ++it) {
            pair_body(pa[it * PAIR_STRIDE],       pb[it * PAIR_STRIDE],
                      pa[it * PAIR_STRIDE + ROWS_ITER],
                      pb[it * PAIR_STRIDE + ROWS_ITER],
                      B, po + (size_t)it * PAIR_STRIDE * M_CONST, true);
        }
    } else {
        for (int rr = r_local; rr < nrows; rr += PAIR_STRIDE) {
            const bool hasB = (rr + ROWS_ITER) < nrows;
            const int  offB = hasB ? ROWS_ITER : 0;
            pair_body(pa[0], pb[0], pa[offB], pb[offB], B, po, hasB);
            po += PAIR_STRIDE * M_CONST;
            pa += PAIR_STRIDE;
            pb += PAIR_STRIDE;
        }
    }
}

extern "C" void kernel_launch(void* const* d_in, const int* in_sizes, int n_in,
                              void* d_out, int out_size) {
    const float* theta       = (const float*)d_in[0];
    const float* basis_mu    = (const float*)d_in[1];
    const float* basis_sigma = (const float*)d_in[2];
    float* out = (float*)d_out;

    const int N = in_sizes[0] / 6;

    const int threads = 256;
    const int blocks  = (N + CHUNK_ROWS - 1) / CHUNK_ROWS;   // 729 for N=131072
    ContinuousSoftmax_kernel<<<blocks, threads>>>(theta, basis_mu, basis_sigma,
                                                  out, N);
}